// round 2
// baseline (speedup 1.0000x reference)
#include <cuda_runtime.h>
#include <math.h>
#include <float.h>

// ---------------- problem constants (fixed shapes) ----------------
#define T_TOK 4096
#define C_SP  4096
#define HID   1024
#define METAF 20
#define SPAND 3092          // 3*HID + METAF
#define UHID  1024
#define M_TOP 1024
#define K_ANT 50
#define NEGV  (-1e30f)

// ---------------- device scratch ----------------------------------
__device__ float g_logits[T_TOK];
__device__ float g_span_emb[(size_t)C_SP * SPAND];
__device__ float g_hid1[(size_t)C_SP * UHID];
__device__ float g_mention[C_SP];
__device__ int   g_topidx[M_TOP];
__device__ float g_topm[M_TOP];
__device__ float g_topemb[(size_t)M_TOP * SPAND];
__device__ float g_tmp[(size_t)M_TOP * SPAND];
__device__ float g_fast[(size_t)M_TOP * M_TOP];

// ---------------- kernel 1: token logits (fp64 accumulate) --------
__global__ void k_token_logits(const float* __restrict__ hs,
                               const float* __restrict__ w_attn,
                               const float* __restrict__ b_attn) {
    int warp = (blockIdx.x * blockDim.x + threadIdx.x) >> 5;
    int lane = threadIdx.x & 31;
    if (warp >= T_TOK) return;
    const float* row = hs + (size_t)warp * HID;
    double acc = 0.0;
    #pragma unroll 8
    for (int i = lane; i < HID; i += 32) acc += (double)row[i] * (double)w_attn[i];
    #pragma unroll
    for (int o = 16; o; o >>= 1) acc += __shfl_xor_sync(0xffffffffu, acc, o);
    if (lane == 0) g_logits[warp] = (float)(acc + (double)b_attn[0]);
}

// ---------------- kernel 2: span embeddings (fp64 pooling) --------
__global__ void k_span_emb(const float* __restrict__ hs,
                           const int* __restrict__ starts,
                           const int* __restrict__ widths,
                           const float* __restrict__ w_width) {
    int c = blockIdx.x;
    int s = starts[c], w = widths[c];
    int e = s + w, L = w + 1;
    __shared__ float p[32];
    int tid = threadIdx.x;
    if (tid < 32) {
        double lg = (tid < L) ? (double)g_logits[s + tid] : -1e300;
        double mx = lg;
        #pragma unroll
        for (int o = 16; o; o >>= 1) {
            double v = __shfl_xor_sync(0xffffffffu, mx, o);
            mx = fmax(mx, v);
        }
        double ex = (tid < L) ? exp(lg - mx) : 0.0;
        double sm = ex;
        #pragma unroll
        for (int o = 16; o; o >>= 1) sm += __shfl_xor_sync(0xffffffffu, sm, o);
        p[tid] = (float)(ex / sm);
    }
    __syncthreads();
    float* out = g_span_emb + (size_t)c * SPAND;
    const float* hrow_s = hs + (size_t)s * HID;
    const float* hrow_e = hs + (size_t)e * HID;
    for (int h = tid; h < HID; h += blockDim.x) {
        out[h]        = hrow_s[h];
        out[HID + h]  = hrow_e[h];
        double acc = 0.0;
        for (int l = 0; l < L; ++l)
            acc += (double)p[l] * (double)hs[(size_t)(s + l) * HID + h];
        out[2 * HID + METAF + h] = (float)acc;
    }
    if (tid < METAF) out[2 * HID + tid] = w_width[w * METAF + tid];
}

// ---------------- Kahan-compensated tiled SGEMM -------------------
// C[M,N] = A[M,K] * op(B) + bias,   op(B)=B[K,N] (NN) or B[N,K]^T (NT)
// Compensated summation keeps |err| ~ 2*eps*|C| regardless of K.
template<int BM, int BN, int TM, int TN, bool RELU, bool NT, bool BIAS>
__global__ void k_gemm_kahan(const float* __restrict__ A, const float* __restrict__ B,
                             const float* __restrict__ bias, float* __restrict__ C,
                             int M, int N, int K) {
    __shared__ float As[16][BM];
    __shared__ float Bs[16][BN];
    const int tid  = threadIdx.x;      // 256 threads
    const int trow = tid >> 4;         // 0..15
    const int tcol = tid & 15;         // 0..15
    const int row0 = blockIdx.y * BM;
    const int col0 = blockIdx.x * BN;

    float acc[TM][TN];
    float cmp[TM][TN];
    #pragma unroll
    for (int i = 0; i < TM; ++i)
        #pragma unroll
        for (int j = 0; j < TN; ++j) { acc[i][j] = 0.f; cmp[i][j] = 0.f; }

    for (int k0 = 0; k0 < K; k0 += 16) {
        #pragma unroll
        for (int i = tid; i < BM * 16; i += 256) {
            int r = i >> 4, kk = i & 15;
            int gr = row0 + r, gk = k0 + kk;
            As[kk][r] = (gr < M && gk < K) ? A[(size_t)gr * K + gk] : 0.f;
        }
        if (!NT) {
            #pragma unroll
            for (int i = tid; i < 16 * BN; i += 256) {
                int kk = i / BN, n = i % BN;
                int gk = k0 + kk, gn = col0 + n;
                Bs[kk][n] = (gk < K && gn < N) ? B[(size_t)gk * N + gn] : 0.f;
            }
        } else {
            #pragma unroll
            for (int i = tid; i < BN * 16; i += 256) {
                int n = i >> 4, kk = i & 15;
                int gn = col0 + n, gk = k0 + kk;
                Bs[kk][n] = (gn < N && gk < K) ? B[(size_t)gn * K + gk] : 0.f;
            }
        }
        __syncthreads();
        #pragma unroll
        for (int kk = 0; kk < 16; ++kk) {
            float a[TM], b[TN];
            #pragma unroll
            for (int i = 0; i < TM; i += 4) {
                float4 t = *(const float4*)&As[kk][trow * TM + i];
                a[i] = t.x; a[i+1] = t.y; a[i+2] = t.z; a[i+3] = t.w;
            }
            #pragma unroll
            for (int j = 0; j < TN; j += 4) {
                float4 t = *(const float4*)&Bs[kk][tcol * TN + j];
                b[j] = t.x; b[j+1] = t.y; b[j+2] = t.z; b[j+3] = t.w;
            }
            #pragma unroll
            for (int i = 0; i < TM; ++i)
                #pragma unroll
                for (int j = 0; j < TN; ++j) {
                    // Kahan: y = a*b - c; t = s + y; c = (t - s) - y; s = t
                    float y = __fmaf_rn(a[i], b[j], -cmp[i][j]);
                    float t = __fadd_rn(acc[i][j], y);
                    cmp[i][j] = __fsub_rn(__fsub_rn(t, acc[i][j]), y);
                    acc[i][j] = t;
                }
        }
        __syncthreads();
    }
    #pragma unroll
    for (int i = 0; i < TM; ++i) {
        int r = row0 + trow * TM + i;
        if (r >= M) continue;
        #pragma unroll
        for (int j = 0; j < TN; ++j) {
            int cc = col0 + tcol * TN + j;
            if (cc >= N) continue;
            float v = acc[i][j];
            if (BIAS) v = __fadd_rn(v, bias[cc]);
            if (RELU) v = fmaxf(v, 0.f);
            C[(size_t)r * N + cc] = v;
        }
    }
}

// ---------------- kernel: mention score (fp64 accumulate) ---------
__global__ void k_score(const float* __restrict__ w_u2,
                        const float* __restrict__ b_u2) {
    int warp = (blockIdx.x * blockDim.x + threadIdx.x) >> 5;
    int lane = threadIdx.x & 31;
    if (warp >= C_SP) return;
    const float* row = g_hid1 + (size_t)warp * UHID;
    double acc = 0.0;
    #pragma unroll 8
    for (int i = lane; i < UHID; i += 32) acc += (double)row[i] * (double)w_u2[i];
    #pragma unroll
    for (int o = 16; o; o >>= 1) acc += __shfl_xor_sync(0xffffffffu, acc, o);
    if (lane == 0) g_mention[warp] = (float)(acc + (double)b_u2[0]);
}

// ---------------- kernel: sort + greedy non-crossing + compact ----
__global__ void k_extract(const int* __restrict__ starts,
                          const int* __restrict__ widths) {
    extern __shared__ int sh[];
    float* key = (float*)sh;           // later reused as latest_end (int)
    int* idx = sh + 4096;
    int* es  = sh + 8192;
    int* flg = sh + 12288;
    const int tid = threadIdx.x;       // 1024 threads

    for (int i = tid; i < C_SP; i += 1024) {
        key[i] = g_mention[i];
        idx[i] = i;
        flg[i] = 0;
    }
    __syncthreads();

    // bitonic sort: descending by score, ties -> ascending index
    for (unsigned k = 2; k <= 4096; k <<= 1) {
        for (unsigned j = k >> 1; j > 0; j >>= 1) {
            for (unsigned t = tid; t < 2048; t += 1024) {
                unsigned i = ((t & ~(j - 1)) << 1) | (t & (j - 1));
                unsigned l = i | j;
                float ki = key[i], kl = key[l];
                int   ii = idx[i], il = idx[l];
                bool before_l_i = (kl > ki) || (kl == ki && il < ii);
                bool dir = ((i & k) == 0);
                if (before_l_i == dir) {
                    key[i] = kl; key[l] = ki;
                    idx[i] = il; idx[l] = ii;
                }
            }
            __syncthreads();
        }
    }

    volatile int* le = (volatile int*)key;
    volatile int* ves = (volatile int*)es;
    for (int i = tid; i < T_TOK; i += 1024) {
        ((int*)key)[i] = -1;
        es[i] = T_TOK;
    }
    __syncthreads();

    // greedy non-crossing, warp 0 only, early exit at count==M_TOP
    if (tid < 32) {
        int lane = tid;
        int count = 0;
        for (int p = 0; p < C_SP && count < M_TOP; ++p) {
            int ci = idx[p];
            int s = starts[ci];
            int w = widths[ci];
            int e = s + w;
            bool crossing = false;
            if (lane < w) {                 // w <= 29 < 32
                crossing = (le[s + 1 + lane] > e) | (ves[s + lane] < s);
            }
            unsigned m = __ballot_sync(0xffffffffu, crossing);
            if (m == 0u) {
                if (lane == 0) {
                    int cur = le[s]; if (e > cur) ((int*)key)[s] = e;
                    int cur2 = ves[e]; if (s < cur2) es[e] = s;
                    flg[ci] = 1;
                }
                count++;
            }
            __syncwarp();
        }
    }
    __syncthreads();

    // compact selected candidate indices (ascending), pad with 4095
    __shared__ int wsum[32];
    __shared__ int woff[33];
    int base = tid * 4;
    int f0 = flg[base], f1 = flg[base + 1], f2 = flg[base + 2], f3 = flg[base + 3];
    int c = f0 + f1 + f2 + f3;
    int inc = c;
    int lane = tid & 31, wid = tid >> 5;
    #pragma unroll
    for (int o = 1; o < 32; o <<= 1) {
        int n = __shfl_up_sync(0xffffffffu, inc, o);
        if (lane >= o) inc += n;
    }
    if (lane == 31) wsum[wid] = inc;
    __syncthreads();
    if (tid == 0) {
        int run = 0;
        for (int i = 0; i < 32; ++i) { woff[i] = run; run += wsum[i]; }
        woff[32] = run;
    }
    __syncthreads();
    int pos = woff[wid] + (inc - c);
    if (f0) { if (pos < M_TOP) g_topidx[pos] = base;     pos++; }
    if (f1) { if (pos < M_TOP) g_topidx[pos] = base + 1; pos++; }
    if (f2) { if (pos < M_TOP) g_topidx[pos] = base + 2; pos++; }
    if (f3) { if (pos < M_TOP) g_topidx[pos] = base + 3; pos++; }
    int total = woff[32];
    for (int p = total + tid; p < M_TOP; p += 1024) g_topidx[p] = C_SP - 1;
}

// ---------------- kernel: gather top spans ------------------------
__global__ void k_gather(float* __restrict__ out_topidx) {
    int p = blockIdx.x;
    int ci = g_topidx[p];
    if (threadIdx.x == 0) {
        g_topm[p] = g_mention[ci];
        out_topidx[p] = (float)ci;
    }
    const float4* src = (const float4*)(g_span_emb + (size_t)ci * SPAND);
    float4* dst = (float4*)(g_topemb + (size_t)p * SPAND);
    for (int i = threadIdx.x; i < SPAND / 4; i += blockDim.x) dst[i] = src[i];
}

// ---------------- kernel: assemble fast scores + per-row top-50 ---
__global__ void k_topk(float* __restrict__ out_ant,
                       float* __restrict__ out_mask,
                       float* __restrict__ out_score) {
    __shared__ float v[M_TOP];
    __shared__ float rv[256];
    __shared__ int   ri[256];
    const int i = blockIdx.x;
    const int tid = threadIdx.x;
    const float mi = g_topm[i];
    for (int j = tid; j < M_TOP; j += 256) {
        // match reference association: ((m_i + m_j) + mask) + dot
        float val = __fadd_rn(__fadd_rn(__fadd_rn(mi, g_topm[j]),
                                        (j < i) ? 0.f : NEGV),
                              g_fast[(size_t)i * M_TOP + j]);
        v[j] = val;
    }
    __syncthreads();
    for (int k = 0; k < K_ANT; ++k) {
        float bv = -INFINITY; int bi = M_TOP;
        for (int j = tid; j < M_TOP; j += 256) {
            float x = v[j];
            if (x > bv || (x == bv && j < bi)) { bv = x; bi = j; }
        }
        rv[tid] = bv; ri[tid] = bi;
        __syncthreads();
        for (int s = 128; s > 0; s >>= 1) {
            if (tid < s) {
                if (rv[tid + s] > rv[tid] ||
                    (rv[tid + s] == rv[tid] && ri[tid + s] < ri[tid])) {
                    rv[tid] = rv[tid + s]; ri[tid] = ri[tid + s];
                }
            }
            __syncthreads();
        }
        if (tid == 0) {
            int j = ri[0];
            out_ant[(size_t)i * K_ANT + k]   = (float)j;
            out_mask[(size_t)i * K_ANT + k]  = (j < i) ? 1.f : 0.f;
            out_score[(size_t)i * K_ANT + k] = rv[0];
            v[j] = -INFINITY;
        }
        __syncthreads();
    }
}

// ---------------- launch ------------------------------------------
extern "C" void kernel_launch(void* const* d_in, const int* in_sizes, int n_in,
                              void* d_out, int out_size) {
    const float* hs      = (const float*)d_in[0];
    const int*   starts  = (const int*)d_in[1];
    const int*   widths  = (const int*)d_in[2];
    int base = 3;
    if (n_in >= 14 && in_sizes[3] == 1 && in_sizes[4] == 1) base = 5;
    const float* w_width = (const float*)d_in[base + 0];
    const float* w_attn  = (const float*)d_in[base + 1];
    const float* b_attn  = (const float*)d_in[base + 2];
    const float* w_u1    = (const float*)d_in[base + 3];
    const float* b_u1    = (const float*)d_in[base + 4];
    const float* w_u2    = (const float*)d_in[base + 5];
    const float* b_u2    = (const float*)d_in[base + 6];
    const float* w_fast  = (const float*)d_in[base + 7];
    const float* b_fast  = (const float*)d_in[base + 8];

    float* out = (float*)d_out;
    float* out_topidx = out;
    float* out_ant    = out + M_TOP;
    float* out_mask   = out + M_TOP + M_TOP * K_ANT;
    float* out_score  = out + M_TOP + 2 * M_TOP * K_ANT;

    float *p_span, *p_hid1, *p_topemb, *p_tmp, *p_fast;
    cudaGetSymbolAddress((void**)&p_span,   g_span_emb);
    cudaGetSymbolAddress((void**)&p_hid1,   g_hid1);
    cudaGetSymbolAddress((void**)&p_topemb, g_topemb);
    cudaGetSymbolAddress((void**)&p_tmp,    g_tmp);
    cudaGetSymbolAddress((void**)&p_fast,   g_fast);

    // 1. token logits (fp64 accumulate)
    k_token_logits<<<T_TOK * 32 / 256, 256>>>(hs, w_attn, b_attn);

    // 2. span embeddings (fp64 softmax pooling)
    k_span_emb<<<C_SP, 256>>>(hs, starts, widths, w_width);

    // 3. hid1 = relu(span_emb @ w_u1 + b_u1)   [4096,1024], Kahan
    {
        dim3 grid((UHID + 63) / 64, (C_SP + 127) / 128);
        k_gemm_kahan<128, 64, 8, 4, true, false, true><<<grid, 256>>>(
            p_span, w_u1, b_u1, p_hid1, C_SP, UHID, SPAND);
    }

    // 4. mention scores (fp64 accumulate)
    k_score<<<C_SP * 32 / 256, 256>>>(w_u2, b_u2);

    // 5. sort + greedy extraction + compact
    cudaFuncSetAttribute(k_extract, cudaFuncAttributeMaxDynamicSharedMemorySize, 65536);
    k_extract<<<1, 1024, 65536>>>(starts, widths);

    // 6. gather top_emb / top_m / write top_idx output
    k_gather<<<M_TOP, 256>>>(out_topidx);

    // 7. tmp = top_emb @ w_fast + b_fast   [1024,3092], Kahan
    {
        dim3 grid((SPAND + 63) / 64, (M_TOP + 127) / 128);
        k_gemm_kahan<128, 64, 8, 4, false, false, true><<<grid, 256>>>(
            p_topemb, w_fast, b_fast, p_tmp, M_TOP, SPAND, SPAND);
    }

    // 8. fast0 = tmp @ top_emb^T   [1024,1024], Kahan
    {
        dim3 grid((M_TOP + 63) / 64, (M_TOP + 63) / 64);
        k_gemm_kahan<64, 64, 4, 4, false, true, false><<<grid, 256>>>(
            p_tmp, p_topemb, nullptr, p_fast, M_TOP, M_TOP, SPAND);
    }

    // 9. assemble fast matrix + per-row top-50
    k_topk<<<M_TOP, 256>>>(out_ant, out_mask, out_score);

    (void)in_sizes; (void)n_in; (void)out_size;
}